// round 6
// baseline (speedup 1.0000x reference)
#include <cuda_runtime.h>
#include <cuda_fp16.h>
#include <math.h>

#define VOL (128*128*128)          // 2^21
#define NB 8                        // batch*channels

// Packed spectra FFT(o + i*t): [vol][kx][z][y], fp16 complex => 67MB
__device__ __half2 g_ft[(size_t)NB * VOL];
// Accumulators: c3*520 + shell*8 + bc ; c3: 0=num, 1=out power, 2=tgt power
__device__ float g_acc[3 * 65 * NB];
__device__ unsigned g_done;        // zero-initialized; restored to 0 each launch

__device__ __forceinline__ float2 cmul(float2 a, float2 b) {
    return make_float2(fmaf(a.x, b.x, -a.y * b.y), fmaf(a.x, b.y, a.y * b.x));
}
__device__ __forceinline__ int rev5(int i) { return (int)(__brev((unsigned)i) >> 27); }

// ---------------------------------------------------------------------------
// 128-point forward FFT within one warp; 4 complex values per lane.
// Output (natural) index i = 4*lane + r. Input loaded bit-reversed:
// v[r] = src[rev5(lane) + {0,64,32,96}[r]].  tw[k]=exp(-2*pi*i*k/128), k<64.
//
// Shuffle stages use multiply-before-exchange (select-free): each lane
// multiplies its own value by its effective twiddle (tw[0]=1 for lo lanes),
// exchanges the product, and combines with one signed FMA pair.
__device__ __forceinline__ void warp_fft128(float2 v[4], int lane, const float2* tw) {
    float2 t;
    // len=2
    t = v[1]; v[1] = make_float2(v[0].x - t.x, v[0].y - t.y);
              v[0] = make_float2(v[0].x + t.x, v[0].y + t.y);
    t = v[3]; v[3] = make_float2(v[2].x - t.x, v[2].y - t.y);
              v[2] = make_float2(v[2].x + t.x, v[2].y + t.y);
    // len=4 : (0,2) w=1 ; (1,3) w=-i
    t = v[2]; v[2] = make_float2(v[0].x - t.x, v[0].y - t.y);
              v[0] = make_float2(v[0].x + t.x, v[0].y + t.y);
    t = make_float2(v[3].y, -v[3].x);
    v[3] = make_float2(v[1].x - t.x, v[1].y - t.y);
    v[1] = make_float2(v[1].x + t.x, v[1].y + t.y);
    // 5 shuffle stages
#pragma unroll
    for (int s = 0; s < 5; s++) {
        int m = 1 << s;
        int bit = (lane >> s) & 1;
        int bmask = -bit;                       // 0 for lo lanes, ~0 for hi
        float sgn = bit ? -1.0f : 1.0f;
        int base = (lane & (m - 1)) << 2;
        int sh = 4 - s;
#pragma unroll
        for (int r = 0; r < 4; r++) {
            int idx = ((base | r) << sh) & bmask;   // lo lanes -> tw[0] = (1,0)
            float2 w = tw[idx];
            float2 p = cmul(w, v[r]);
            float2 op;
            op.x = __shfl_xor_sync(0xffffffffu, p.x, m);
            op.y = __shfl_xor_sync(0xffffffffu, p.y, m);
            v[r] = make_float2(fmaf(sgn, p.x, op.x), fmaf(sgn, p.y, op.y));
        }
    }
}

__device__ __forceinline__ void init_tw(float2* tw, int tid) {
    if (tid < 64) {
        float sv, cv;
        sincosf(-6.283185307179586f * (float)tid * (1.0f / 128.0f), &sv, &cv);
        tw[tid] = make_float2(cv, sv);
    }
}

// ---------------------------------------------------------------------------
// Pass 1: pack P = o + i*t, x-FFT, write fp16 transposed to [vol][kx][z][y].
__global__ void __launch_bounds__(1024) k_fft_x(const float* __restrict__ a_in,
                                                const float* __restrict__ b_in) {
    __shared__ float2 tw[64];
    __shared__ __half2 tile[32][129];
    int tid = threadIdx.x, lane = tid & 31, w = tid >> 5;
    init_tw(tw, tid);

    unsigned b = blockIdx.x;              // 8 vols * 128 z * 4 ytiles = 4096
    unsigned ytile = b & 3u;
    unsigned z     = (b >> 2) & 127u;
    unsigned vol   = b >> 9;

    size_t off = (size_t)vol * VOL + (size_t)z * 16384 + (size_t)(ytile * 32 + w) * 128;
    const float* so = a_in + off;
    const float* st = b_in + off;
    __syncthreads();                      // tw ready

    int rb = rev5(lane);
    float2 v[4];
    v[0] = make_float2(so[rb],      st[rb]);
    v[1] = make_float2(so[rb + 64], st[rb + 64]);
    v[2] = make_float2(so[rb + 32], st[rb + 32]);
    v[3] = make_float2(so[rb + 96], st[rb + 96]);
    warp_fft128(v, lane, tw);

    const float sc = 0.08838834764831845f;    // 1/sqrt(128)
#pragma unroll
    for (int r = 0; r < 4; r++)
        tile[w][4 * lane + r] = __float22half2_rn(make_float2(v[r].x * sc, v[r].y * sc));
    __syncthreads();

    size_t base = (size_t)vol * VOL + (size_t)z * 128 + ytile * 32 + lane;
#pragma unroll
    for (int xi = 0; xi < 4; xi++) {
        int kx = w * 4 + xi;
        g_ft[base + (size_t)kx * 16384] = tile[lane][kx];
    }
}

// ---------------------------------------------------------------------------
// Pass 2: per (bc, kx-pair): load plane(s), y-FFT in smem, z-FFT in REGISTERS
// (column of A + mirror column of B per warp), shuffle Hermitian pairing,
// shell-reduce. Last block computes the loss and resets global state.
#define SMEM2 (64 * 8 + 2 * 128 * 129 * 4 + 32 * 196 * 4)

__global__ void __launch_bounds__(1024, 1) k_fft_yz_reduce(float* __restrict__ out) {
    extern __shared__ unsigned char smem_raw[];
    float2*  tw   = (float2*)smem_raw;                    // 512B
    __half2* pA   = (__half2*)(smem_raw + 512);           // [z][y] pitch 129
    __half2* pBs  = pA + 128 * 129;
    float*   bins = (float*)(pBs + 128 * 129);            // [warp][196]
    __shared__ bool s_last;
    __shared__ float red[NB];

    int tid = threadIdx.x, lane = tid & 31, w = tid >> 5;
    init_tw(tw, tid);
    for (int i = tid; i < 32 * 196; i += 1024) bins[i] = 0.0f;

    unsigned bc  = blockIdx.x / 65;
    unsigned kx1 = blockIdx.x % 65;
    unsigned kx2 = (128u - kx1) & 127u;
    bool dual = (kx2 != kx1);
    __half2* pB = dual ? pBs : pA;

    const __half2* gA = g_ft + ((size_t)bc * 128 + kx1) * 16384;
    const __half2* gB = g_ft + ((size_t)bc * 128 + kx2) * 16384;
#pragma unroll
    for (int i = 0; i < 16; i++) {
        int idx = tid + i * 1024;
        int z = idx >> 7, y = idx & 127;
        pA[z * 129 + y] = gA[idx];
        if (dual) pBs[z * 129 + y] = gB[idx];
    }
    __syncthreads();

    int rb = rev5(lane);
    const float sc = 0.08838834764831845f;
    int npl = dual ? 2 : 1;

    // y-FFT in place: 128 rows per plane, 4 per warp
    for (int p = 0; p < npl; p++) {
        __half2* pl = p ? pBs : pA;
#pragma unroll
        for (int i = 0; i < 4; i++) {
            __half2* rowp = pl + (w + 32 * i) * 129;
            float2 v[4];
            v[0] = __half22float2(rowp[rb]);
            v[1] = __half22float2(rowp[rb + 64]);
            v[2] = __half22float2(rowp[rb + 32]);
            v[3] = __half22float2(rowp[rb + 96]);
            warp_fft128(v, lane, tw);
#pragma unroll
            for (int r = 0; r < 4; r++)
                rowp[4 * lane + r] = __float22half2_rn(make_float2(v[r].x * sc, v[r].y * sc));
        }
    }
    __syncthreads();

    // z-FFT in registers + shuffle-paired Hermitian split + shell reduce.
    // Warp handles column yA of plane A and mirror column yB of plane B.
    // z-norm (1/128 on products) folded into cfac.
    int fx = (int)kx1; if (fx >= 64) fx -= 128;
    float cfac = dual ? (0.5f / 128.0f) : (0.25f / 128.0f);
    float* mybins = bins + w * 196;

#pragma unroll
    for (int i = 0; i < 4; i++) {
        int yA = w + 32 * i;
        int yB = (128 - yA) & 127;

        // mirror column first: FFT, then shuffle-gather F(-k); vb dies early
        float2 Fm[4];
        {
            float2 vb[4];
            vb[0] = __half22float2(pB[ rb       * 129 + yB]);
            vb[1] = __half22float2(pB[(rb + 64) * 129 + yB]);
            vb[2] = __half22float2(pB[(rb + 32) * 129 + yB]);
            vb[3] = __half22float2(pB[(rb + 96) * 129 + yB]);
            warp_fft128(vb, lane, tw);
            // pair slot kz=4*lane+r with index (128-kz)&127 of this column
            int l0 = (32 - lane) & 31, l1 = 31 - lane;
            Fm[0].x = __shfl_sync(0xffffffffu, vb[0].x, l0);
            Fm[0].y = __shfl_sync(0xffffffffu, vb[0].y, l0);
            Fm[1].x = __shfl_sync(0xffffffffu, vb[3].x, l1);
            Fm[1].y = __shfl_sync(0xffffffffu, vb[3].y, l1);
            Fm[2].x = __shfl_sync(0xffffffffu, vb[2].x, l1);
            Fm[2].y = __shfl_sync(0xffffffffu, vb[2].y, l1);
            Fm[3].x = __shfl_sync(0xffffffffu, vb[1].x, l1);
            Fm[3].y = __shfl_sync(0xffffffffu, vb[1].y, l1);
        }

        float2 va[4];
        va[0] = __half22float2(pA[ rb       * 129 + yA]);
        va[1] = __half22float2(pA[(rb + 64) * 129 + yA]);
        va[2] = __half22float2(pA[(rb + 32) * 129 + yA]);
        va[3] = __half22float2(pA[(rb + 96) * 129 + yA]);
        warp_fft128(va, lane, tw);

        int fy = (yA >= 64) ? yA - 128 : yA;
        int fxy2 = fx * fx + fy * fy;
#pragma unroll
        for (int r = 0; r < 4; r++) {
            int kz = 4 * lane + r;
            int fz = (kz >= 64) ? kz - 128 : kz;
            int r2 = fz * fz + fxy2;
            int sh = (int)sqrtf((float)r2);          // exact truncation
            if (sh <= 64) {
                float2 F = va[r];
                float Ox = F.x + Fm[r].x, Oy = F.y - Fm[r].y;   // 2*O
                float Tx = F.y + Fm[r].y, Ty = Fm[r].x - F.x;   // 2*T
                atomicAdd(&mybins[sh * 3 + 0], cfac * (Ox * Tx + Oy * Ty));
                atomicAdd(&mybins[sh * 3 + 1], cfac * (Ox * Ox + Oy * Oy));
                atomicAdd(&mybins[sh * 3 + 2], cfac * (Tx * Tx + Ty * Ty));
            }
        }
    }
    __syncthreads();

    // fold per-warp bins -> global accumulators
    if (tid < 195) {
        float s = 0.0f;
#pragma unroll
        for (int ww = 0; ww < 32; ww++) s += bins[ww * 196 + tid];
        int sh = tid / 3, c3 = tid % 3;
        atomicAdd(&g_acc[c3 * 520 + sh * 8 + bc], s);
    }
    __syncthreads();

    // completion counter; last block computes the loss and resets state
    if (tid == 0) {
        __threadfence();
        unsigned old = atomicAdd(&g_done, 1u);
        s_last = (old == gridDim.x - 1);
    }
    __syncthreads();
    if (!s_last) return;

    float* sacc = bins;   // reuse smem
    for (int i = tid; i < 3 * 65 * NB; i += 1024)
        sacc[i] = atomicExch(&g_acc[i], 0.0f);    // read + reset for next replay
    __syncthreads();

    if (tid < NB) {
        float acc = 0.0f;
        for (int s = 1; s <= 64; s++) {
            float n  = sacc[0 * 520 + s * 8 + tid];
            float po = sacc[1 * 520 + s * 8 + tid];
            float pt = sacc[2 * 520 + s * 8 + tid];
            float f = n / sqrtf(po * pt + 1e-6f);
            acc += fminf(1.0f, fmaxf(-1.0f, f));
        }
        red[tid] = 1.0f - acc * (1.0f / 64.0f);
    }
    __syncthreads();
    if (tid == 0) {
        float m = 0.0f;
#pragma unroll
        for (int i = 0; i < NB; i++) m += red[i];
        out[0] = m * (1.0f / (float)NB);
        atomicExch(&g_done, 0u);
    }
}

// ---------------------------------------------------------------------------
extern "C" void kernel_launch(void* const* d_in, const int* in_sizes, int n_in,
                              void* d_out, int out_size) {
    const float* model_output = (const float*)d_in[0];
    const float* target       = (const float*)d_in[1];

    cudaFuncSetAttribute(k_fft_yz_reduce,
                         cudaFuncAttributeMaxDynamicSharedMemorySize, SMEM2);

    k_fft_x<<<8 * 128 * 4, 1024>>>(model_output, target);
    k_fft_yz_reduce<<<8 * 65, 1024, SMEM2>>>((float*)d_out);
}

// round 7
// speedup vs baseline: 1.5295x; 1.5295x over previous
#include <cuda_runtime.h>
#include <cuda_fp16.h>
#include <math.h>

#define VOL (128*128*128)          // 2^21
#define NB 8                        // batch*channels

// Packed spectra FFT(o + i*t): [vol][p][z][y] where plane p holds true kx=rev7(p)
__device__ __half2 g_ft[(size_t)NB * VOL];
// Accumulators: c3*520 + shell*8 + bc
__device__ float g_acc[3 * 65 * NB];
__device__ unsigned g_done;

__device__ __forceinline__ float2 cmul(float2 a, float2 b) {
    return make_float2(fmaf(a.x, b.x, -a.y * b.y), fmaf(a.x, b.y, a.y * b.x));
}
__device__ __forceinline__ int rev5(int i) { return (int)(__brev((unsigned)i) >> 27); }
__device__ __forceinline__ int rev7(int i) { return (int)(__brev((unsigned)i) >> 25); }

// ---------------------------------------------------------------------------
// Twiddle tables (all conflict-free, lane-indexed):
//  twA[64]    = exp(-2*pi*i*k/128)
//  twB[32]    = twA[2*lane]
//  twS[4][32] = stage m=16>>j: (lane&m) ? twA[(lane&(m-1))*(64/m)] : (1,0)
#define TABS_F2 (64 + 32 + 128)
__device__ __forceinline__ void init_tabs(float2* twA, float2* twB, float2* twS, int tid) {
    const float K = -0.04908738521234052f;   // -2*pi/128
    if (tid < 64) {
        float sv, cv; sincosf(K * (float)tid, &sv, &cv);
        twA[tid] = make_float2(cv, sv);
    }
    if (tid < 32) {
        float sv, cv; sincosf(K * (float)(2 * tid), &sv, &cv);
        twB[tid] = make_float2(cv, sv);
#pragma unroll
        for (int j = 0; j < 4; j++) {
            int m = 16 >> j;
            float2 val = make_float2(1.0f, 0.0f);
            if (tid & m) {
                int idx = (tid & (m - 1)) * (64 / m);
                float s2, c2; sincosf(K * (float)idx, &s2, &c2);
                val = make_float2(c2, s2);
            }
            twS[j * 32 + tid] = val;
        }
    }
}

// ---------------------------------------------------------------------------
// 128-pt DIF FFT within a warp. Element mapping: slot (lane, r) holds x[lane+32r]
// on input (natural order); on output holds X[rev7(lane+32r)] (bit-reversed).
__device__ __forceinline__ void dif_fft128(float2 v[4], int lane,
        const float2* twA, const float2* twB, const float2* twS) {
    float2 a, b, w;
    // half=64 (intra-lane): (v0,v2) w=twA[lane]; (v1,v3) w=twA[lane+32]
    w = twA[lane];
    a = v[0]; b = v[2];
    v[0] = make_float2(a.x + b.x, a.y + b.y);
    v[2] = cmul(w, make_float2(a.x - b.x, a.y - b.y));
    w = twA[lane + 32];
    a = v[1]; b = v[3];
    v[1] = make_float2(a.x + b.x, a.y + b.y);
    v[3] = cmul(w, make_float2(a.x - b.x, a.y - b.y));
    // half=32 (intra-lane): (v0,v1),(v2,v3) w=twB[lane]
    w = twB[lane];
    a = v[0]; b = v[1];
    v[0] = make_float2(a.x + b.x, a.y + b.y);
    v[1] = cmul(w, make_float2(a.x - b.x, a.y - b.y));
    a = v[2]; b = v[3];
    v[2] = make_float2(a.x + b.x, a.y + b.y);
    v[3] = cmul(w, make_float2(a.x - b.x, a.y - b.y));
    // shuffle stages m = 16,8,4,2 : t = oth + sgn*mine ; v = w_lane * t
#pragma unroll
    for (int j = 0; j < 4; j++) {
        int m = 16 >> j;
        float sgn = (lane & m) ? -1.0f : 1.0f;
        float2 wj = twS[j * 32 + lane];
#pragma unroll
        for (int r = 0; r < 4; r++) {
            float2 mine = v[r];
            float2 oth;
            oth.x = __shfl_xor_sync(0xffffffffu, mine.x, m);
            oth.y = __shfl_xor_sync(0xffffffffu, mine.y, m);
            float2 t = make_float2(fmaf(sgn, mine.x, oth.x), fmaf(sgn, mine.y, oth.y));
            v[r] = cmul(wj, t);
        }
    }
    // m=1, w=1: pure add/sub
    {
        float sgn = (lane & 1) ? -1.0f : 1.0f;
#pragma unroll
        for (int r = 0; r < 4; r++) {
            float2 mine = v[r];
            float2 oth;
            oth.x = __shfl_xor_sync(0xffffffffu, mine.x, 1);
            oth.y = __shfl_xor_sync(0xffffffffu, mine.y, 1);
            v[r] = make_float2(fmaf(sgn, mine.x, oth.x), fmaf(sgn, mine.y, oth.y));
        }
    }
}

// ---------------------------------------------------------------------------
// Pass 1: pack P = o + i*t, x-FFT (DIF), fp16 transposed to [vol][p][z][y].
__global__ void __launch_bounds__(1024) k_fft_x(const float* __restrict__ a_in,
                                                const float* __restrict__ b_in) {
    __shared__ float2 tabs[TABS_F2];
    __shared__ __half2 tile[32][129];
    float2* twA = tabs; float2* twB = tabs + 64; float2* twS = tabs + 96;
    int tid = threadIdx.x, lane = tid & 31, w = tid >> 5;
    init_tabs(twA, twB, twS, tid);

    unsigned b = blockIdx.x;              // 8 vols * 128 z * 4 ytiles = 4096
    unsigned ytile = b & 3u;
    unsigned z     = (b >> 2) & 127u;
    unsigned vol   = b >> 9;

    size_t off = (size_t)vol * VOL + (size_t)z * 16384 + (size_t)(ytile * 32 + w) * 128;
    const float* so = a_in + off;
    const float* st = b_in + off;
    __syncthreads();                      // tables ready

    float2 v[4];
#pragma unroll
    for (int r = 0; r < 4; r++)
        v[r] = make_float2(so[lane + 32 * r], st[lane + 32 * r]);
    dif_fft128(v, lane, twA, twB, twS);

    const float sc = 0.08838834764831845f;    // 1/sqrt(128)
#pragma unroll
    for (int r = 0; r < 4; r++)
        tile[w][lane + 32 * r] = __float22half2_rn(make_float2(v[r].x * sc, v[r].y * sc));
    __syncthreads();

    size_t base = (size_t)vol * VOL + (size_t)z * 128 + ytile * 32 + lane;
#pragma unroll
    for (int xi = 0; xi < 4; xi++) {
        int p = w * 4 + xi;               // bit-reversed kx label
        g_ft[base + (size_t)p * 16384] = tile[lane][p];
    }
}

// ---------------------------------------------------------------------------
// Pass 2: per (bc, true-kx pair): load plane(s) at rev7(kx), y-FFT in smem
// (output ky bit-reversed), z-FFT in registers with Hermitian shuffle pairing,
// shell-reduce. Last block computes the loss and resets global state.
#define SMEM2 (TABS_F2 * 8 + 2 * 128 * 129 * 4 + 32 * 196 * 4)

__global__ void __launch_bounds__(1024, 1) k_fft_yz_reduce(float* __restrict__ out) {
    extern __shared__ unsigned char smem_raw[];
    float2*  tabs = (float2*)smem_raw;
    float2*  twA = tabs; float2* twB = tabs + 64; float2* twS = tabs + 96;
    __half2* pA   = (__half2*)(tabs + TABS_F2);           // [z][y] pitch 129
    __half2* pBs  = pA + 128 * 129;
    float*   bins = (float*)(pBs + 128 * 129);            // [warp][196]
    __shared__ bool s_last;
    __shared__ float red[NB];

    int tid = threadIdx.x, lane = tid & 31, w = tid >> 5;
    init_tabs(twA, twB, twS, tid);
    for (int i = tid; i < 32 * 196; i += 1024) bins[i] = 0.0f;

    unsigned bc  = blockIdx.x / 65;
    unsigned kx1 = blockIdx.x % 65;                       // true kx 0..64
    unsigned kx2 = (128u - kx1) & 127u;
    bool dual = (kx2 != kx1);
    int p1 = rev7((int)kx1), p2 = rev7((int)kx2);
    __half2* pB = dual ? pBs : pA;

    const __half2* gA = g_ft + ((size_t)bc * 128 + p1) * 16384;
    const __half2* gB = g_ft + ((size_t)bc * 128 + p2) * 16384;
#pragma unroll
    for (int i = 0; i < 16; i++) {
        int idx = tid + i * 1024;
        int z = idx >> 7, y = idx & 127;
        pA[z * 129 + y] = gA[idx];
        if (dual) pBs[z * 129 + y] = gB[idx];
    }
    __syncthreads();

    const float sc = 0.08838834764831845f;
    int npl = dual ? 2 : 1;

    // y-FFT in place: rows natural-y in, bit-reversed-ky out
    for (int p = 0; p < npl; p++) {
        __half2* pl = p ? pBs : pA;
#pragma unroll
        for (int i = 0; i < 4; i++) {
            __half2* rowp = pl + (w + 32 * i) * 129;
            float2 v[4];
#pragma unroll
            for (int r = 0; r < 4; r++) v[r] = __half22float2(rowp[lane + 32 * r]);
            dif_fft128(v, lane, twA, twB, twS);
#pragma unroll
            for (int r = 0; r < 4; r++)
                rowp[lane + 32 * r] = __float22half2_rn(make_float2(v[r].x * sc, v[r].y * sc));
        }
    }
    __syncthreads();

    // z-FFT in registers + Hermitian pairing + shell reduce.
    // slot (lane,r) of z-FFT output holds kz = 4*rev5(lane) + {0,2,1,3}[r]
    int fx = (int)kx1; if (fx >= 64) fx -= 128;
    float cfac = dual ? (0.5f / 128.0f) : (0.25f / 128.0f);
    float* mybins = bins + w * 196;

    int qz = rev5(lane);
    int l1 = 31 - lane;
    int l0 = rev5((32 - qz) & 31);
    int kzv[4] = { 4 * qz, 4 * qz + 2, 4 * qz + 1, 4 * qz + 3 };
    int fzv[4];
#pragma unroll
    for (int r = 0; r < 4; r++) fzv[r] = (kzv[r] >= 64) ? kzv[r] - 128 : kzv[r];

#pragma unroll
    for (int i = 0; i < 4; i++) {
        int pyA = w + 32 * i;                 // column position (bit-reversed ky)
        int kyA = rev7(pyA);
        int fy = (kyA >= 64) ? kyA - 128 : kyA;
        int fxy2 = fx * fx + fy * fy;
        if (fxy2 > 4224) continue;            // no shell <= 64 possible (warp-uniform)
        int pyB = rev7((128 - kyA) & 127);

        // mirror column of plane B: FFT then shuffle-gather F(-kz)
        float2 Fm[4];
        {
            float2 vb[4];
#pragma unroll
            for (int r = 0; r < 4; r++)
                vb[r] = __half22float2(pB[(lane + 32 * r) * 129 + pyB]);
            dif_fft128(vb, lane, twA, twB, twS);
            Fm[0].x = __shfl_sync(0xffffffffu, vb[0].x, l0);
            Fm[0].y = __shfl_sync(0xffffffffu, vb[0].y, l0);
            Fm[1].x = __shfl_sync(0xffffffffu, vb[1].x, l1);
            Fm[1].y = __shfl_sync(0xffffffffu, vb[1].y, l1);
            Fm[2].x = __shfl_sync(0xffffffffu, vb[3].x, l1);
            Fm[2].y = __shfl_sync(0xffffffffu, vb[3].y, l1);
            Fm[3].x = __shfl_sync(0xffffffffu, vb[2].x, l1);
            Fm[3].y = __shfl_sync(0xffffffffu, vb[2].y, l1);
        }

        float2 va[4];
#pragma unroll
        for (int r = 0; r < 4; r++)
            va[r] = __half22float2(pA[(lane + 32 * r) * 129 + pyA]);
        dif_fft128(va, lane, twA, twB, twS);

#pragma unroll
        for (int r = 0; r < 4; r++) {
            int r2 = fzv[r] * fzv[r] + fxy2;
            int sh = (int)sqrtf((float)r2);    // exact truncation
            if (sh <= 64) {
                float2 F = va[r];
                float Ox = F.x + Fm[r].x, Oy = F.y - Fm[r].y;   // 2*O
                float Tx = F.y + Fm[r].y, Ty = Fm[r].x - F.x;   // 2*T
                atomicAdd(&mybins[sh * 3 + 0], cfac * (Ox * Tx + Oy * Ty));
                atomicAdd(&mybins[sh * 3 + 1], cfac * (Ox * Ox + Oy * Oy));
                atomicAdd(&mybins[sh * 3 + 2], cfac * (Tx * Tx + Ty * Ty));
            }
        }
    }
    __syncthreads();

    // fold per-warp bins -> global accumulators
    if (tid < 195) {
        float s = 0.0f;
#pragma unroll
        for (int ww = 0; ww < 32; ww++) s += bins[ww * 196 + tid];
        int sh = tid / 3, c3 = tid % 3;
        atomicAdd(&g_acc[c3 * 520 + sh * 8 + bc], s);
    }
    __syncthreads();

    // last block computes loss and resets state (graph-replay safe)
    if (tid == 0) {
        __threadfence();
        unsigned old = atomicAdd(&g_done, 1u);
        s_last = (old == gridDim.x - 1);
    }
    __syncthreads();
    if (!s_last) return;

    float* sacc = bins;
    for (int i = tid; i < 3 * 65 * NB; i += 1024)
        sacc[i] = atomicExch(&g_acc[i], 0.0f);
    __syncthreads();

    if (tid < NB) {
        float acc = 0.0f;
        for (int s = 1; s <= 64; s++) {
            float n  = sacc[0 * 520 + s * 8 + tid];
            float po = sacc[1 * 520 + s * 8 + tid];
            float pt = sacc[2 * 520 + s * 8 + tid];
            float f = n / sqrtf(po * pt + 1e-6f);
            acc += fminf(1.0f, fmaxf(-1.0f, f));
        }
        red[tid] = 1.0f - acc * (1.0f / 64.0f);
    }
    __syncthreads();
    if (tid == 0) {
        float m = 0.0f;
#pragma unroll
        for (int i = 0; i < NB; i++) m += red[i];
        out[0] = m * (1.0f / (float)NB);
        atomicExch(&g_done, 0u);
    }
}

// ---------------------------------------------------------------------------
extern "C" void kernel_launch(void* const* d_in, const int* in_sizes, int n_in,
                              void* d_out, int out_size) {
    const float* model_output = (const float*)d_in[0];
    const float* target       = (const float*)d_in[1];

    cudaFuncSetAttribute(k_fft_yz_reduce,
                         cudaFuncAttributeMaxDynamicSharedMemorySize, SMEM2);

    k_fft_x<<<8 * 128 * 4, 1024>>>(model_output, target);
    k_fft_yz_reduce<<<8 * 65, 1024, SMEM2>>>((float*)d_out);
}

// round 8
// speedup vs baseline: 1.6941x; 1.1077x over previous
#include <cuda_runtime.h>
#include <cuda_fp16.h>
#include <math.h>

#define VOL (128*128*128)          // 2^21
#define NB 8                        // batch*channels

// Packed spectra FFT(o + i*t): [vol][p][z][y] where plane p holds true kx=rev7(p)
__device__ __half2 g_ft[(size_t)NB * VOL];
// Accumulators: c3*520 + shell*8 + bc
__device__ float g_acc[3 * 65 * NB];
__device__ unsigned g_done;

__device__ __forceinline__ float2 cmul(float2 a, float2 b) {
    return make_float2(fmaf(a.x, b.x, -a.y * b.y), fmaf(a.x, b.y, a.y * b.x));
}
__device__ __forceinline__ int rev5(int i) { return (int)(__brev((unsigned)i) >> 27); }
__device__ __forceinline__ int rev7(int i) { return (int)(__brev((unsigned)i) >> 25); }

// ===========================================================================
// fp32 tables + DIF FFT (pass 1)
#define TABS_F2 (64 + 32 + 128)
__device__ __forceinline__ void init_tabs(float2* twA, float2* twB, float2* twS, int tid) {
    const float K = -0.04908738521234052f;   // -2*pi/128
    if (tid < 64) {
        float sv, cv; sincosf(K * (float)tid, &sv, &cv);
        twA[tid] = make_float2(cv, sv);
    }
    if (tid < 32) {
        float sv, cv; sincosf(K * (float)(2 * tid), &sv, &cv);
        twB[tid] = make_float2(cv, sv);
#pragma unroll
        for (int j = 0; j < 4; j++) {
            int m = 16 >> j;
            float2 val = make_float2(1.0f, 0.0f);
            if (tid & m) {
                int idx = (tid & (m - 1)) * (64 / m);
                float s2, c2; sincosf(K * (float)idx, &s2, &c2);
                val = make_float2(c2, s2);
            }
            twS[j * 32 + tid] = val;
        }
    }
}

// 128-pt DIF FFT (fp32). Slot (lane,r) holds x[lane+32r] in, X[rev7(lane+32r)] out.
__device__ __forceinline__ void dif_fft128(float2 v[4], int lane,
        const float2* twA, const float2* twB, const float2* twS) {
    float2 a, b, w;
    w = twA[lane];
    a = v[0]; b = v[2];
    v[0] = make_float2(a.x + b.x, a.y + b.y);
    v[2] = cmul(w, make_float2(a.x - b.x, a.y - b.y));
    w = twA[lane + 32];
    a = v[1]; b = v[3];
    v[1] = make_float2(a.x + b.x, a.y + b.y);
    v[3] = cmul(w, make_float2(a.x - b.x, a.y - b.y));
    w = twB[lane];
    a = v[0]; b = v[1];
    v[0] = make_float2(a.x + b.x, a.y + b.y);
    v[1] = cmul(w, make_float2(a.x - b.x, a.y - b.y));
    a = v[2]; b = v[3];
    v[2] = make_float2(a.x + b.x, a.y + b.y);
    v[3] = cmul(w, make_float2(a.x - b.x, a.y - b.y));
#pragma unroll
    for (int j = 0; j < 4; j++) {
        int m = 16 >> j;
        float sgn = (lane & m) ? -1.0f : 1.0f;
        float2 wj = twS[j * 32 + lane];
#pragma unroll
        for (int r = 0; r < 4; r++) {
            float2 mine = v[r];
            float2 oth;
            oth.x = __shfl_xor_sync(0xffffffffu, mine.x, m);
            oth.y = __shfl_xor_sync(0xffffffffu, mine.y, m);
            float2 t = make_float2(fmaf(sgn, mine.x, oth.x), fmaf(sgn, mine.y, oth.y));
            v[r] = cmul(wj, t);
        }
    }
    {
        float sgn = (lane & 1) ? -1.0f : 1.0f;
#pragma unroll
        for (int r = 0; r < 4; r++) {
            float2 mine = v[r];
            float2 oth;
            oth.x = __shfl_xor_sync(0xffffffffu, mine.x, 1);
            oth.y = __shfl_xor_sync(0xffffffffu, mine.y, 1);
            v[r] = make_float2(fmaf(sgn, mine.x, oth.x), fmaf(sgn, mine.y, oth.y));
        }
    }
}

// ===========================================================================
// fp16 tables + DIF FFT (pass 2). Twiddle stored as pair (wr,wr),(-wi,wi).
struct __align__(8) h2pair { __half2 rr, ii; };
#define TABS_H (64 + 32 + 128)

__device__ __forceinline__ void init_tabs_h(h2pair* twA, h2pair* twB, h2pair* twS, int tid) {
    const float K = -0.04908738521234052f;
    if (tid < 64) {
        float sv, cv; sincosf(K * (float)tid, &sv, &cv);
        twA[tid].rr = __floats2half2_rn(cv, cv);
        twA[tid].ii = __floats2half2_rn(-sv, sv);
    }
    if (tid < 32) {
        float sv, cv; sincosf(K * (float)(2 * tid), &sv, &cv);
        twB[tid].rr = __floats2half2_rn(cv, cv);
        twB[tid].ii = __floats2half2_rn(-sv, sv);
#pragma unroll
        for (int j = 0; j < 4; j++) {
            int m = 16 >> j;
            float c2 = 1.0f, s2 = 0.0f;
            if (tid & m) {
                int idx = (tid & (m - 1)) * (64 / m);
                sincosf(K * (float)idx, &s2, &c2);
            }
            twS[j * 32 + tid].rr = __floats2half2_rn(c2, c2);
            twS[j * 32 + tid].ii = __floats2half2_rn(-s2, s2);
        }
    }
}

__device__ __forceinline__ __half2 cmul_h(h2pair w, __half2 v) {
    return __hfma2(w.ii, __lowhigh2highlow(v), __hmul2(w.rr, v));
}
__device__ __forceinline__ __half2 shflx_h2(__half2 v, int m) {
    unsigned u = *reinterpret_cast<unsigned*>(&v);
    u = __shfl_xor_sync(0xffffffffu, u, m);
    return *reinterpret_cast<__half2*>(&u);
}
__device__ __forceinline__ __half2 shfl_h2(__half2 v, int src) {
    unsigned u = *reinterpret_cast<unsigned*>(&v);
    u = __shfl_sync(0xffffffffu, u, src);
    return *reinterpret_cast<__half2*>(&u);
}
__device__ __forceinline__ __half2 sgn_h2(int hi) {
    unsigned u = hi ? 0xBC00BC00u : 0x3C003C00u;   // (-1,-1) : (1,1)
    return *reinterpret_cast<__half2*>(&u);
}

// 128-pt DIF FFT in fp16x2. Same index mapping as the fp32 version.
__device__ __forceinline__ void dif_fft128_h(__half2 v[4], int lane,
        const h2pair* twA, const h2pair* twB, const h2pair* twS) {
    __half2 a, b;
    a = v[0]; b = v[2];
    v[0] = __hadd2(a, b);
    v[2] = cmul_h(twA[lane], __hsub2(a, b));
    a = v[1]; b = v[3];
    v[1] = __hadd2(a, b);
    v[3] = cmul_h(twA[lane + 32], __hsub2(a, b));
    {
        h2pair w = twB[lane];
        a = v[0]; b = v[1];
        v[0] = __hadd2(a, b);
        v[1] = cmul_h(w, __hsub2(a, b));
        a = v[2]; b = v[3];
        v[2] = __hadd2(a, b);
        v[3] = cmul_h(w, __hsub2(a, b));
    }
#pragma unroll
    for (int j = 0; j < 4; j++) {
        int m = 16 >> j;
        __half2 sg = sgn_h2(lane & m);
        h2pair wj = twS[j * 32 + lane];
#pragma unroll
        for (int r = 0; r < 4; r++) {
            __half2 oth = shflx_h2(v[r], m);
            v[r] = cmul_h(wj, __hfma2(sg, v[r], oth));
        }
    }
    {
        __half2 sg = sgn_h2(lane & 1);
#pragma unroll
        for (int r = 0; r < 4; r++) {
            __half2 oth = shflx_h2(v[r], 1);
            v[r] = __hfma2(sg, v[r], oth);
        }
    }
}

// ---------------------------------------------------------------------------
// Pass 1: pack P = o + i*t, x-FFT fp32 (DIF), fp16 transposed to [vol][p][z][y].
__global__ void __launch_bounds__(1024) k_fft_x(const float* __restrict__ a_in,
                                                const float* __restrict__ b_in) {
    __shared__ float2 tabs[TABS_F2];
    __shared__ __half2 tile[32][129];
    float2* twA = tabs; float2* twB = tabs + 64; float2* twS = tabs + 96;
    int tid = threadIdx.x, lane = tid & 31, w = tid >> 5;
    init_tabs(twA, twB, twS, tid);

    unsigned b = blockIdx.x;              // 8 vols * 128 z * 4 ytiles = 4096
    unsigned ytile = b & 3u;
    unsigned z     = (b >> 2) & 127u;
    unsigned vol   = b >> 9;

    size_t off = (size_t)vol * VOL + (size_t)z * 16384 + (size_t)(ytile * 32 + w) * 128;
    const float* so = a_in + off;
    const float* st = b_in + off;
    __syncthreads();

    float2 v[4];
#pragma unroll
    for (int r = 0; r < 4; r++)
        v[r] = make_float2(so[lane + 32 * r], st[lane + 32 * r]);
    dif_fft128(v, lane, twA, twB, twS);

    const float sc = 0.08838834764831845f;    // 1/sqrt(128)
#pragma unroll
    for (int r = 0; r < 4; r++)
        tile[w][lane + 32 * r] = __float22half2_rn(make_float2(v[r].x * sc, v[r].y * sc));
    __syncthreads();

    size_t base = (size_t)vol * VOL + (size_t)z * 128 + ytile * 32 + lane;
#pragma unroll
    for (int xi = 0; xi < 4; xi++) {
        int p = w * 4 + xi;               // bit-reversed kx label
        g_ft[base + (size_t)p * 16384] = tile[lane][p];
    }
}

// ---------------------------------------------------------------------------
// Pass 2: per (bc, true-kx pair): load plane(s) at rev7(kx), fp16 y-FFT in smem,
// fp16 z-FFT in registers with Hermitian shuffle pairing, fp32 shell reduce.
#define SMEM2 (TABS_H * 8 + 2 * 128 * 129 * 4 + 32 * 196 * 4)

__global__ void __launch_bounds__(1024, 1) k_fft_yz_reduce(float* __restrict__ out) {
    extern __shared__ unsigned char smem_raw[];
    h2pair*  tabs = (h2pair*)smem_raw;
    h2pair*  twA = tabs; h2pair* twB = tabs + 64; h2pair* twS = tabs + 96;
    __half2* pA   = (__half2*)(tabs + TABS_H);            // [z][y] pitch 129
    __half2* pBs  = pA + 128 * 129;
    float*   bins = (float*)(pBs + 128 * 129);            // [warp][196]
    __shared__ bool s_last;
    __shared__ float red[NB];

    int tid = threadIdx.x, lane = tid & 31, w = tid >> 5;
    init_tabs_h(twA, twB, twS, tid);
    for (int i = tid; i < 32 * 196; i += 1024) bins[i] = 0.0f;

    unsigned bc  = blockIdx.x / 65;
    unsigned kx1 = blockIdx.x % 65;                       // true kx 0..64
    unsigned kx2 = (128u - kx1) & 127u;
    bool dual = (kx2 != kx1);
    int p1 = rev7((int)kx1), p2 = rev7((int)kx2);
    __half2* pB = dual ? pBs : pA;

    const __half2* gA = g_ft + ((size_t)bc * 128 + p1) * 16384;
    const __half2* gB = g_ft + ((size_t)bc * 128 + p2) * 16384;
#pragma unroll
    for (int i = 0; i < 16; i++) {
        int idx = tid + i * 1024;
        int z = idx >> 7, y = idx & 127;
        pA[z * 129 + y] = gA[idx];
        if (dual) pBs[z * 129 + y] = gB[idx];
    }
    __syncthreads();

    const __half2 sch = __floats2half2_rn(0.08838834764831845f, 0.08838834764831845f);
    int npl = dual ? 2 : 1;

    // y-FFT in place (fp16): rows natural-y in, bit-reversed-ky out
    for (int p = 0; p < npl; p++) {
        __half2* pl = p ? pBs : pA;
#pragma unroll
        for (int i = 0; i < 4; i++) {
            __half2* rowp = pl + (w + 32 * i) * 129;
            __half2 v[4];
#pragma unroll
            for (int r = 0; r < 4; r++) v[r] = rowp[lane + 32 * r];
            dif_fft128_h(v, lane, twA, twB, twS);
#pragma unroll
            for (int r = 0; r < 4; r++) rowp[lane + 32 * r] = __hmul2(v[r], sch);
        }
    }
    __syncthreads();

    // z-FFT (fp16, registers) + Hermitian pairing + fp32 shell reduce.
    // slot (lane,r) of z-FFT output holds kz = 4*rev5(lane) + {0,2,1,3}[r]
    int fx = (int)kx1; if (fx >= 64) fx -= 128;
    float cfac = dual ? (0.5f / 128.0f) : (0.25f / 128.0f);
    float* mybins = bins + w * 196;

    int qz = rev5(lane);
    int l1 = 31 - lane;
    int l0 = rev5((32 - qz) & 31);
    int kzv[4] = { 4 * qz, 4 * qz + 2, 4 * qz + 1, 4 * qz + 3 };
    int fzv[4];
#pragma unroll
    for (int r = 0; r < 4; r++) fzv[r] = (kzv[r] >= 64) ? kzv[r] - 128 : kzv[r];

#pragma unroll
    for (int i = 0; i < 4; i++) {
        int pyA = w + 32 * i;                 // column position (bit-reversed ky)
        int kyA = rev7(pyA);
        int fy = (kyA >= 64) ? kyA - 128 : kyA;
        int fxy2 = fx * fx + fy * fy;
        if (fxy2 > 4224) continue;            // no shell <= 64 possible (warp-uniform)
        int pyB = rev7((128 - kyA) & 127);

        // mirror column of plane B: FFT then shuffle-gather F(-kz)
        __half2 Fm[4];
        {
            __half2 vb[4];
#pragma unroll
            for (int r = 0; r < 4; r++)
                vb[r] = pB[(lane + 32 * r) * 129 + pyB];
            dif_fft128_h(vb, lane, twA, twB, twS);
            Fm[0] = shfl_h2(vb[0], l0);
            Fm[1] = shfl_h2(vb[1], l1);
            Fm[2] = shfl_h2(vb[3], l1);
            Fm[3] = shfl_h2(vb[2], l1);
        }

        __half2 va[4];
#pragma unroll
        for (int r = 0; r < 4; r++)
            va[r] = pA[(lane + 32 * r) * 129 + pyA];
        dif_fft128_h(va, lane, twA, twB, twS);

#pragma unroll
        for (int r = 0; r < 4; r++) {
            int r2 = fzv[r] * fzv[r] + fxy2;
            int sh = (int)sqrtf((float)r2);    // exact truncation
            if (sh <= 64) {
                float2 F = __half22float2(va[r]);
                float2 M = __half22float2(Fm[r]);
                float Ox = F.x + M.x, Oy = F.y - M.y;   // 2*O
                float Tx = F.y + M.y, Ty = M.x - F.x;   // 2*T
                atomicAdd(&mybins[sh * 3 + 0], cfac * (Ox * Tx + Oy * Ty));
                atomicAdd(&mybins[sh * 3 + 1], cfac * (Ox * Ox + Oy * Oy));
                atomicAdd(&mybins[sh * 3 + 2], cfac * (Tx * Tx + Ty * Ty));
            }
        }
    }
    __syncthreads();

    // fold per-warp bins -> global accumulators
    if (tid < 195) {
        float s = 0.0f;
#pragma unroll
        for (int ww = 0; ww < 32; ww++) s += bins[ww * 196 + tid];
        int sh = tid / 3, c3 = tid % 3;
        atomicAdd(&g_acc[c3 * 520 + sh * 8 + bc], s);
    }
    __syncthreads();

    // last block computes loss and resets state (graph-replay safe)
    if (tid == 0) {
        __threadfence();
        unsigned old = atomicAdd(&g_done, 1u);
        s_last = (old == gridDim.x - 1);
    }
    __syncthreads();
    if (!s_last) return;

    float* sacc = bins;
    for (int i = tid; i < 3 * 65 * NB; i += 1024)
        sacc[i] = atomicExch(&g_acc[i], 0.0f);
    __syncthreads();

    if (tid < NB) {
        float acc = 0.0f;
        for (int s = 1; s <= 64; s++) {
            float n  = sacc[0 * 520 + s * 8 + tid];
            float po = sacc[1 * 520 + s * 8 + tid];
            float pt = sacc[2 * 520 + s * 8 + tid];
            float f = n / sqrtf(po * pt + 1e-6f);
            acc += fminf(1.0f, fmaxf(-1.0f, f));
        }
        red[tid] = 1.0f - acc * (1.0f / 64.0f);
    }
    __syncthreads();
    if (tid == 0) {
        float m = 0.0f;
#pragma unroll
        for (int i = 0; i < NB; i++) m += red[i];
        out[0] = m * (1.0f / (float)NB);
        atomicExch(&g_done, 0u);
    }
}

// ---------------------------------------------------------------------------
extern "C" void kernel_launch(void* const* d_in, const int* in_sizes, int n_in,
                              void* d_out, int out_size) {
    const float* model_output = (const float*)d_in[0];
    const float* target       = (const float*)d_in[1];

    cudaFuncSetAttribute(k_fft_yz_reduce,
                         cudaFuncAttributeMaxDynamicSharedMemorySize, SMEM2);

    k_fft_x<<<8 * 128 * 4, 1024>>>(model_output, target);
    k_fft_yz_reduce<<<8 * 65, 1024, SMEM2>>>((float*)d_out);
}

// round 9
// speedup vs baseline: 1.7903x; 1.0568x over previous
#include <cuda_runtime.h>
#include <cuda_fp16.h>
#include <math.h>

#define VOL (128*128*128)          // 2^21
#define NB 8                        // batch*channels

// Packed spectra FFT(o + i*t): [vol][p][z][y] where plane p holds true kx=rev7(p)
__device__ __half2 g_ft[(size_t)NB * VOL];
// Accumulators: c3*520 + shell*8 + bc
__device__ float g_acc[3 * 65 * NB];
__device__ unsigned g_done;

__device__ __forceinline__ int rev5(int i) { return (int)(__brev((unsigned)i) >> 27); }
__device__ __forceinline__ int rev7(int i) { return (int)(__brev((unsigned)i) >> 25); }

// ===========================================================================
// fp16 twiddle tables. Twiddle stored as pair (wr,wr),(-wi,wi).
// The 1/sqrt(128) ortho scale is folded into the m=2 stage table (twS[3]):
// every element passes that stage exactly once.
struct __align__(8) h2pair { __half2 rr, ii; };
#define TABS_H (64 + 32 + 128)

__device__ __forceinline__ void init_tabs_h(h2pair* twA, h2pair* twB, h2pair* twS, int tid) {
    const float K = -0.04908738521234052f;   // -2*pi/128
    const float SC = 0.08838834764831845f;   // 1/sqrt(128)
    if (tid < 64) {
        float sv, cv; sincosf(K * (float)tid, &sv, &cv);
        twA[tid].rr = __floats2half2_rn(cv, cv);
        twA[tid].ii = __floats2half2_rn(-sv, sv);
    }
    if (tid < 32) {
        float sv, cv; sincosf(K * (float)(2 * tid), &sv, &cv);
        twB[tid].rr = __floats2half2_rn(cv, cv);
        twB[tid].ii = __floats2half2_rn(-sv, sv);
#pragma unroll
        for (int j = 0; j < 4; j++) {
            int m = 16 >> j;
            float c2 = 1.0f, s2 = 0.0f;
            if (tid & m) {
                int idx = (tid & (m - 1)) * (64 / m);
                sincosf(K * (float)idx, &s2, &c2);
            }
            float g = (j == 3) ? SC : 1.0f;    // fold ortho scale into m=2 stage
            twS[j * 32 + tid].rr = __floats2half2_rn(c2 * g, c2 * g);
            twS[j * 32 + tid].ii = __floats2half2_rn(-s2 * g, s2 * g);
        }
    }
}

__device__ __forceinline__ __half2 cmul_h(h2pair w, __half2 v) {
    return __hfma2(w.ii, __lowhigh2highlow(v), __hmul2(w.rr, v));
}
__device__ __forceinline__ __half2 shflx_h2(__half2 v, int m) {
    unsigned u = *reinterpret_cast<unsigned*>(&v);
    u = __shfl_xor_sync(0xffffffffu, u, m);
    return *reinterpret_cast<__half2*>(&u);
}
__device__ __forceinline__ __half2 sgn_h2(int hi) {
    unsigned u = hi ? 0xBC00BC00u : 0x3C003C00u;   // (-1,-1) : (1,1)
    return *reinterpret_cast<__half2*>(&u);
}
__device__ __forceinline__ __half2 conj_h2(__half2 v) {
    unsigned c = 0xBC003C00u;                      // (1, -1)
    return __hmul2(v, *reinterpret_cast<__half2*>(&c));
}

// 128-pt DIF FFT in fp16x2. Slot (lane,r) holds x[lane+32r] in,
// sc*X[rev7(lane+32r)] out (scale from twS[3]).
__device__ __forceinline__ void dif_fft128_h(__half2 v[4], int lane,
        const h2pair* twA, const h2pair* twB, const h2pair* twS) {
    __half2 a, b;
    a = v[0]; b = v[2];
    v[0] = __hadd2(a, b);
    v[2] = cmul_h(twA[lane], __hsub2(a, b));
    a = v[1]; b = v[3];
    v[1] = __hadd2(a, b);
    v[3] = cmul_h(twA[lane + 32], __hsub2(a, b));
    {
        h2pair w = twB[lane];
        a = v[0]; b = v[1];
        v[0] = __hadd2(a, b);
        v[1] = cmul_h(w, __hsub2(a, b));
        a = v[2]; b = v[3];
        v[2] = __hadd2(a, b);
        v[3] = cmul_h(w, __hsub2(a, b));
    }
#pragma unroll
    for (int j = 0; j < 4; j++) {
        int m = 16 >> j;
        __half2 sg = sgn_h2(lane & m);
        h2pair wj = twS[j * 32 + lane];
#pragma unroll
        for (int r = 0; r < 4; r++) {
            __half2 oth = shflx_h2(v[r], m);
            v[r] = cmul_h(wj, __hfma2(sg, v[r], oth));
        }
    }
    {
        __half2 sg = sgn_h2(lane & 1);
#pragma unroll
        for (int r = 0; r < 4; r++) {
            __half2 oth = shflx_h2(v[r], 1);
            v[r] = __hfma2(sg, v[r], oth);
        }
    }
}

// ---------------------------------------------------------------------------
// Pass 1: pack P = o + i*t (fp16), x-FFT fp16, transposed to [vol][p][z][y].
__global__ void __launch_bounds__(1024) k_fft_x(const float* __restrict__ a_in,
                                                const float* __restrict__ b_in) {
    __shared__ h2pair tabs[TABS_H];
    __shared__ __half2 tile[32][129];
    h2pair* twA = tabs; h2pair* twB = tabs + 64; h2pair* twS = tabs + 96;
    int tid = threadIdx.x, lane = tid & 31, w = tid >> 5;
    init_tabs_h(twA, twB, twS, tid);

    unsigned b = blockIdx.x;              // 8 vols * 128 z * 4 ytiles = 4096
    unsigned ytile = b & 3u;
    unsigned z     = (b >> 2) & 127u;
    unsigned vol   = b >> 9;

    size_t off = (size_t)vol * VOL + (size_t)z * 16384 + (size_t)(ytile * 32 + w) * 128;
    const float* so = a_in + off;
    const float* st = b_in + off;
    __syncthreads();

    __half2 v[4];
#pragma unroll
    for (int r = 0; r < 4; r++)
        v[r] = __floats2half2_rn(so[lane + 32 * r], st[lane + 32 * r]);
    dif_fft128_h(v, lane, twA, twB, twS);

#pragma unroll
    for (int r = 0; r < 4; r++)
        tile[w][lane + 32 * r] = v[r];
    __syncthreads();

    size_t base = (size_t)vol * VOL + (size_t)z * 128 + ytile * 32 + lane;
#pragma unroll
    for (int xi = 0; xi < 4; xi++) {
        int p = w * 4 + xi;               // bit-reversed kx label
        g_ft[base + (size_t)p * 16384] = tile[lane][p];
    }
}

// ---------------------------------------------------------------------------
// Pass 2: per (bc, true-kx pair): load plane(s) at rev7(kx), fp16 y-FFT in smem,
// fp16 z-FFT in registers; mirror spectrum via conjugate-input FFT (same-lane
// Hermitian pairing, no shuffles); fp32 shell reduce.
#define SMEM2 (TABS_H * 8 + 2 * 128 * 129 * 4 + 32 * 196 * 4)

__global__ void __launch_bounds__(1024, 1) k_fft_yz_reduce(float* __restrict__ out) {
    extern __shared__ unsigned char smem_raw[];
    h2pair*  tabs = (h2pair*)smem_raw;
    h2pair*  twA = tabs; h2pair* twB = tabs + 64; h2pair* twS = tabs + 96;
    __half2* pA   = (__half2*)(tabs + TABS_H);            // [z][y] pitch 129
    __half2* pBs  = pA + 128 * 129;
    float*   bins = (float*)(pBs + 128 * 129);            // [warp][196]
    __shared__ bool s_last;
    __shared__ float red[NB];

    int tid = threadIdx.x, lane = tid & 31, w = tid >> 5;
    init_tabs_h(twA, twB, twS, tid);
    for (int i = tid; i < 32 * 196; i += 1024) bins[i] = 0.0f;

    unsigned bc  = blockIdx.x / 65;
    unsigned kx1 = blockIdx.x % 65;                       // true kx 0..64
    unsigned kx2 = (128u - kx1) & 127u;
    bool dual = (kx2 != kx1);
    int p1 = rev7((int)kx1), p2 = rev7((int)kx2);
    __half2* pB = dual ? pBs : pA;

    const __half2* gA = g_ft + ((size_t)bc * 128 + p1) * 16384;
    const __half2* gB = g_ft + ((size_t)bc * 128 + p2) * 16384;
#pragma unroll
    for (int i = 0; i < 16; i++) {
        int idx = tid + i * 1024;
        int z = idx >> 7, y = idx & 127;
        pA[z * 129 + y] = gA[idx];
        if (dual) pBs[z * 129 + y] = gB[idx];
    }
    __syncthreads();

    int npl = dual ? 2 : 1;

    // y-FFT in place (fp16, scale in tables): natural-y in, bit-reversed-ky out
    for (int p = 0; p < npl; p++) {
        __half2* pl = p ? pBs : pA;
#pragma unroll
        for (int i = 0; i < 4; i++) {
            __half2* rowp = pl + (w + 32 * i) * 129;
            __half2 v[4];
#pragma unroll
            for (int r = 0; r < 4; r++) v[r] = rowp[lane + 32 * r];
            dif_fft128_h(v, lane, twA, twB, twS);
#pragma unroll
            for (int r = 0; r < 4; r++) rowp[lane + 32 * r] = v[r];
        }
    }
    __syncthreads();

    // z-FFT (fp16, registers). Mirror value F(-k) obtained by FFT-ing the
    // CONJUGATED mirror column: FFT(conj g)(k) = conj(G(-k)) -> same slot as
    // F(k); the conj folds into sign flips in the O/T combine.
    // slot (lane,r) holds kz = 4*rev5(lane) + {0,2,1,3}[r]
    int fx = (int)kx1; if (fx >= 64) fx -= 128;
    float cfac = dual ? 0.5f : 0.25f;     // z-norm now inside the FFT scale
    float* mybins = bins + w * 196;

    int qz = rev5(lane);
    int kzv[4] = { 4 * qz, 4 * qz + 2, 4 * qz + 1, 4 * qz + 3 };
    int fzv[4];
#pragma unroll
    for (int r = 0; r < 4; r++) fzv[r] = (kzv[r] >= 64) ? kzv[r] - 128 : kzv[r];

#pragma unroll
    for (int i = 0; i < 4; i++) {
        int pyA = w + 32 * i;                 // column position (bit-reversed ky)
        int kyA = rev7(pyA);
        int fy = (kyA >= 64) ? kyA - 128 : kyA;
        int fxy2 = fx * fx + fy * fy;
        if (fxy2 > 4224) continue;            // no shell <= 64 possible (warp-uniform)
        int pyB = rev7((128 - kyA) & 127);

        // mirror column of plane B, conjugated then FFT'd
        __half2 vh[4];
#pragma unroll
        for (int r = 0; r < 4; r++)
            vh[r] = conj_h2(pB[(lane + 32 * r) * 129 + pyB]);
        dif_fft128_h(vh, lane, twA, twB, twS);

        __half2 va[4];
#pragma unroll
        for (int r = 0; r < 4; r++)
            va[r] = pA[(lane + 32 * r) * 129 + pyA];
        dif_fft128_h(va, lane, twA, twB, twS);

#pragma unroll
        for (int r = 0; r < 4; r++) {
            int r2 = fzv[r] * fzv[r] + fxy2;
            int sh = (int)sqrtf((float)r2);    // exact truncation
            if (sh <= 64) {
                float2 F = __half22float2(va[r]);
                float2 H = __half22float2(vh[r]);   // H = conj(F(-k)) => M=(H.x,-H.y)
                float Ox = F.x + H.x, Oy = F.y + H.y;   // 2*O
                float Tx = F.y - H.y, Ty = H.x - F.x;   // 2*T
                atomicAdd(&mybins[sh * 3 + 0], Ox * Tx + Oy * Ty);
                atomicAdd(&mybins[sh * 3 + 1], Ox * Ox + Oy * Oy);
                atomicAdd(&mybins[sh * 3 + 2], Tx * Tx + Ty * Ty);
            }
        }
    }
    __syncthreads();

    // fold per-warp bins -> global accumulators (cfac applied once here)
    if (tid < 195) {
        float s = 0.0f;
#pragma unroll
        for (int ww = 0; ww < 32; ww++) s += bins[ww * 196 + tid];
        int sh = tid / 3, c3 = tid % 3;
        atomicAdd(&g_acc[c3 * 520 + sh * 8 + bc], s * cfac);
    }
    __syncthreads();

    // last block computes loss and resets state (graph-replay safe)
    if (tid == 0) {
        __threadfence();
        unsigned old = atomicAdd(&g_done, 1u);
        s_last = (old == gridDim.x - 1);
    }
    __syncthreads();
    if (!s_last) return;

    float* sacc = bins;
    for (int i = tid; i < 3 * 65 * NB; i += 1024)
        sacc[i] = atomicExch(&g_acc[i], 0.0f);
    __syncthreads();

    if (tid < NB) {
        float acc = 0.0f;
        for (int s = 1; s <= 64; s++) {
            float n  = sacc[0 * 520 + s * 8 + tid];
            float po = sacc[1 * 520 + s * 8 + tid];
            float pt = sacc[2 * 520 + s * 8 + tid];
            float f = n / sqrtf(po * pt + 1e-6f);
            acc += fminf(1.0f, fmaxf(-1.0f, f));
        }
        red[tid] = 1.0f - acc * (1.0f / 64.0f);
    }
    __syncthreads();
    if (tid == 0) {
        float m = 0.0f;
#pragma unroll
        for (int i = 0; i < NB; i++) m += red[i];
        out[0] = m * (1.0f / (float)NB);
        atomicExch(&g_done, 0u);
    }
}

// ---------------------------------------------------------------------------
extern "C" void kernel_launch(void* const* d_in, const int* in_sizes, int n_in,
                              void* d_out, int out_size) {
    const float* model_output = (const float*)d_in[0];
    const float* target       = (const float*)d_in[1];

    cudaFuncSetAttribute(k_fft_yz_reduce,
                         cudaFuncAttributeMaxDynamicSharedMemorySize, SMEM2);

    k_fft_x<<<8 * 128 * 4, 1024>>>(model_output, target);
    k_fft_yz_reduce<<<8 * 65, 1024, SMEM2>>>((float*)d_out);
}

// round 10
// speedup vs baseline: 1.8526x; 1.0348x over previous
#include <cuda_runtime.h>
#include <cuda_fp16.h>
#include <math.h>

#define VOL (128*128*128)          // 2^21
#define NB 8                        // batch*channels

// Packed spectra FFT(o + i*t): [vol][p][z][y] where plane p holds true kx=rev7(p)
__device__ __half2 g_ft[(size_t)NB * VOL];
// Accumulators: c3*520 + shell*8 + bc
__device__ float g_acc[3 * 65 * NB];
__device__ unsigned g_done;

__device__ __forceinline__ int rev5(int i) { return (int)(__brev((unsigned)i) >> 27); }
__device__ __forceinline__ int rev7(int i) { return (int)(__brev((unsigned)i) >> 25); }

// ===========================================================================
// fp16 twiddle tables. Twiddle stored as pair (wr,wr),(-wi,wi).
// The 1/sqrt(128) ortho scale is folded into the m=2 stage table (twS[3]).
struct __align__(8) h2pair { __half2 rr, ii; };
#define TABS_H (64 + 32 + 128)

__device__ __forceinline__ void init_tabs_h(h2pair* twA, h2pair* twB, h2pair* twS, int tid) {
    const float K = -0.04908738521234052f;   // -2*pi/128
    const float SC = 0.08838834764831845f;   // 1/sqrt(128)
    if (tid < 64) {
        float sv, cv; sincosf(K * (float)tid, &sv, &cv);
        twA[tid].rr = __floats2half2_rn(cv, cv);
        twA[tid].ii = __floats2half2_rn(-sv, sv);
    }
    if (tid < 32) {
        float sv, cv; sincosf(K * (float)(2 * tid), &sv, &cv);
        twB[tid].rr = __floats2half2_rn(cv, cv);
        twB[tid].ii = __floats2half2_rn(-sv, sv);
#pragma unroll
        for (int j = 0; j < 4; j++) {
            int m = 16 >> j;
            float c2 = 1.0f, s2 = 0.0f;
            if (tid & m) {
                int idx = (tid & (m - 1)) * (64 / m);
                sincosf(K * (float)idx, &s2, &c2);
            }
            float g = (j == 3) ? SC : 1.0f;    // fold ortho scale into m=2 stage
            twS[j * 32 + tid].rr = __floats2half2_rn(c2 * g, c2 * g);
            twS[j * 32 + tid].ii = __floats2half2_rn(-s2 * g, s2 * g);
        }
    }
}

__device__ __forceinline__ __half2 cmul_h(h2pair w, __half2 v) {
    return __hfma2(w.ii, __lowhigh2highlow(v), __hmul2(w.rr, v));
}
__device__ __forceinline__ __half2 shflx_h2(__half2 v, int m) {
    unsigned u = *reinterpret_cast<unsigned*>(&v);
    u = __shfl_xor_sync(0xffffffffu, u, m);
    return *reinterpret_cast<__half2*>(&u);
}
__device__ __forceinline__ __half2 sgn_h2(int hi) {
    unsigned u = hi ? 0xBC00BC00u : 0x3C003C00u;   // (-1,-1) : (1,1)
    return *reinterpret_cast<__half2*>(&u);
}
__device__ __forceinline__ __half2 conj_h2(__half2 v) {
    unsigned c = 0xBC003C00u;                      // (1, -1)
    return __hmul2(v, *reinterpret_cast<__half2*>(&c));
}

// TWO interleaved 128-pt DIF FFTs in fp16x2 (shared twiddles, 2x ILP).
// Slot (lane,r) holds x[lane+32r] in, sc*X[rev7(lane+32r)] out.
__device__ __forceinline__ void dif_fft128_h2(__half2 v[4], __half2 u[4], int lane,
        const h2pair* twA, const h2pair* twB, const h2pair* twS) {
    __half2 a, b;
    {
        h2pair w0 = twA[lane], w1 = twA[lane + 32];
        a = v[0]; b = v[2]; v[0] = __hadd2(a, b); v[2] = cmul_h(w0, __hsub2(a, b));
        a = u[0]; b = u[2]; u[0] = __hadd2(a, b); u[2] = cmul_h(w0, __hsub2(a, b));
        a = v[1]; b = v[3]; v[1] = __hadd2(a, b); v[3] = cmul_h(w1, __hsub2(a, b));
        a = u[1]; b = u[3]; u[1] = __hadd2(a, b); u[3] = cmul_h(w1, __hsub2(a, b));
    }
    {
        h2pair w0 = twB[lane];
        a = v[0]; b = v[1]; v[0] = __hadd2(a, b); v[1] = cmul_h(w0, __hsub2(a, b));
        a = v[2]; b = v[3]; v[2] = __hadd2(a, b); v[3] = cmul_h(w0, __hsub2(a, b));
        a = u[0]; b = u[1]; u[0] = __hadd2(a, b); u[1] = cmul_h(w0, __hsub2(a, b));
        a = u[2]; b = u[3]; u[2] = __hadd2(a, b); u[3] = cmul_h(w0, __hsub2(a, b));
    }
#pragma unroll
    for (int j = 0; j < 4; j++) {
        int m = 16 >> j;
        __half2 sg = sgn_h2(lane & m);
        h2pair wj = twS[j * 32 + lane];
#pragma unroll
        for (int r = 0; r < 4; r++) {
            __half2 o1 = shflx_h2(v[r], m);
            __half2 o2 = shflx_h2(u[r], m);
            v[r] = cmul_h(wj, __hfma2(sg, v[r], o1));
            u[r] = cmul_h(wj, __hfma2(sg, u[r], o2));
        }
    }
    {
        __half2 sg = sgn_h2(lane & 1);
#pragma unroll
        for (int r = 0; r < 4; r++) {
            __half2 o1 = shflx_h2(v[r], 1);
            __half2 o2 = shflx_h2(u[r], 1);
            v[r] = __hfma2(sg, v[r], o1);
            u[r] = __hfma2(sg, u[r], o2);
        }
    }
}

// ---------------------------------------------------------------------------
// Pass 1: pack P = o + i*t (fp16), x-FFT fp16 (2 rows per warp, interleaved),
// transposed to [vol][p][z][y].
__global__ void __launch_bounds__(1024) k_fft_x(const float* __restrict__ a_in,
                                                const float* __restrict__ b_in) {
    __shared__ h2pair tabs[TABS_H];
    __shared__ __half2 tile[64][129];
    h2pair* twA = tabs; h2pair* twB = tabs + 64; h2pair* twS = tabs + 96;
    int tid = threadIdx.x, lane = tid & 31, w = tid >> 5;
    init_tabs_h(twA, twB, twS, tid);

    unsigned b = blockIdx.x;              // 8 vols * 128 z * 2 ytiles = 2048
    unsigned ytile = b & 1u;
    unsigned z     = (b >> 1) & 127u;
    unsigned vol   = b >> 8;

    size_t off = (size_t)vol * VOL + (size_t)z * 16384 + (size_t)(ytile * 64 + w) * 128;
    const float* so = a_in + off;
    const float* st = b_in + off;
    __syncthreads();

    __half2 v[4], u[4];
#pragma unroll
    for (int r = 0; r < 4; r++) {
        v[r] = __floats2half2_rn(so[lane + 32 * r],        st[lane + 32 * r]);
        u[r] = __floats2half2_rn(so[lane + 32 * r + 4096], st[lane + 32 * r + 4096]);
    }
    dif_fft128_h2(v, u, lane, twA, twB, twS);

#pragma unroll
    for (int r = 0; r < 4; r++) {
        tile[w][lane + 32 * r]      = v[r];
        tile[w + 32][lane + 32 * r] = u[r];
    }
    __syncthreads();

    size_t base = (size_t)vol * VOL + (size_t)z * 128 + ytile * 64 + lane;
#pragma unroll
    for (int xi = 0; xi < 4; xi++) {
        int p = w * 4 + xi;               // bit-reversed kx label
        g_ft[base + (size_t)p * 16384]      = tile[lane][p];
        g_ft[base + (size_t)p * 16384 + 32] = tile[lane + 32][p];
    }
}

// ---------------------------------------------------------------------------
// Pass 2: per (bc, true-kx pair): load plane(s) at rev7(kx), fp16 y-FFT in smem
// (row pairs interleaved), fp16 z-FFT in registers (column + conj-mirror column
// interleaved, same-lane Hermitian pairing), fp32 shell reduce.
#define SMEM2 (TABS_H * 8 + 2 * 128 * 129 * 4 + 32 * 196 * 4)

__global__ void __launch_bounds__(1024, 1) k_fft_yz_reduce(float* __restrict__ out) {
    extern __shared__ unsigned char smem_raw[];
    h2pair*  tabs = (h2pair*)smem_raw;
    h2pair*  twA = tabs; h2pair* twB = tabs + 64; h2pair* twS = tabs + 96;
    __half2* pA   = (__half2*)(tabs + TABS_H);            // [z][y] pitch 129
    __half2* pBs  = pA + 128 * 129;
    float*   bins = (float*)(pBs + 128 * 129);            // [warp][196]
    __shared__ bool s_last;
    __shared__ float red[NB];

    int tid = threadIdx.x, lane = tid & 31, w = tid >> 5;
    init_tabs_h(twA, twB, twS, tid);
    for (int i = tid; i < 32 * 196; i += 1024) bins[i] = 0.0f;

    unsigned bc  = blockIdx.x / 65;
    unsigned kx1 = blockIdx.x % 65;                       // true kx 0..64
    unsigned kx2 = (128u - kx1) & 127u;
    bool dual = (kx2 != kx1);
    int p1 = rev7((int)kx1), p2 = rev7((int)kx2);
    __half2* pB = dual ? pBs : pA;

    const __half2* gA = g_ft + ((size_t)bc * 128 + p1) * 16384;
    const __half2* gB = g_ft + ((size_t)bc * 128 + p2) * 16384;
#pragma unroll
    for (int i = 0; i < 16; i++) {
        int idx = tid + i * 1024;
        int z = idx >> 7, y = idx & 127;
        pA[z * 129 + y] = gA[idx];
        if (dual) pBs[z * 129 + y] = gB[idx];
    }
    __syncthreads();

    int npl = dual ? 2 : 1;

    // y-FFT in place (fp16, scale in tables): row pairs (w+64i, w+64i+32)
    for (int p = 0; p < npl; p++) {
        __half2* pl = p ? pBs : pA;
#pragma unroll
        for (int i = 0; i < 2; i++) {
            __half2* row0 = pl + (w + 64 * i) * 129;
            __half2* row1 = pl + (w + 64 * i + 32) * 129;
            __half2 v[4], u[4];
#pragma unroll
            for (int r = 0; r < 4; r++) {
                v[r] = row0[lane + 32 * r];
                u[r] = row1[lane + 32 * r];
            }
            dif_fft128_h2(v, u, lane, twA, twB, twS);
#pragma unroll
            for (int r = 0; r < 4; r++) {
                row0[lane + 32 * r] = v[r];
                row1[lane + 32 * r] = u[r];
            }
        }
    }
    __syncthreads();

    // z-FFT (fp16, registers). Mirror value F(-k) via FFT of the CONJUGATED
    // mirror column (same slot as F(k)); conj folds into O/T sign flips.
    // slot (lane,r) holds kz = 4*rev5(lane) + {0,2,1,3}[r]
    int fx = (int)kx1; if (fx >= 64) fx -= 128;
    float cfac = dual ? 0.5f : 0.25f;     // z-norm inside the FFT scale
    float* mybins = bins + w * 196;

    int qz = rev5(lane);
    int kzv[4] = { 4 * qz, 4 * qz + 2, 4 * qz + 1, 4 * qz + 3 };
    int fzv[4];
#pragma unroll
    for (int r = 0; r < 4; r++) fzv[r] = (kzv[r] >= 64) ? kzv[r] - 128 : kzv[r];

#pragma unroll
    for (int i = 0; i < 4; i++) {
        int pyA = w + 32 * i;                 // column position (bit-reversed ky)
        int kyA = rev7(pyA);
        int fy = (kyA >= 64) ? kyA - 128 : kyA;
        int fxy2 = fx * fx + fy * fy;
        if (fxy2 > 4224) continue;            // no shell <= 64 possible (warp-uniform)
        int pyB = rev7((128 - kyA) & 127);

        __half2 va[4], vh[4];
#pragma unroll
        for (int r = 0; r < 4; r++) {
            va[r] = pA[(lane + 32 * r) * 129 + pyA];
            vh[r] = conj_h2(pB[(lane + 32 * r) * 129 + pyB]);
        }
        dif_fft128_h2(va, vh, lane, twA, twB, twS);

#pragma unroll
        for (int r = 0; r < 4; r++) {
            int r2 = fzv[r] * fzv[r] + fxy2;
            int sh = (int)sqrtf((float)r2);    // exact truncation
            if (sh <= 64) {
                float2 F = __half22float2(va[r]);
                float2 H = __half22float2(vh[r]);   // H = conj(F(-k))
                float Ox = F.x + H.x, Oy = F.y + H.y;   // 2*O
                float Tx = F.y - H.y, Ty = H.x - F.x;   // 2*T
                atomicAdd(&mybins[sh * 3 + 0], Ox * Tx + Oy * Ty);
                atomicAdd(&mybins[sh * 3 + 1], Ox * Ox + Oy * Oy);
                atomicAdd(&mybins[sh * 3 + 2], Tx * Tx + Ty * Ty);
            }
        }
    }
    __syncthreads();

    // fold per-warp bins -> global accumulators (cfac applied once here)
    if (tid < 195) {
        float s = 0.0f;
#pragma unroll
        for (int ww = 0; ww < 32; ww++) s += bins[ww * 196 + tid];
        int sh = tid / 3, c3 = tid % 3;
        atomicAdd(&g_acc[c3 * 520 + sh * 8 + bc], s * cfac);
    }
    __syncthreads();

    // last block computes loss and resets state (graph-replay safe)
    if (tid == 0) {
        __threadfence();
        unsigned old = atomicAdd(&g_done, 1u);
        s_last = (old == gridDim.x - 1);
    }
    __syncthreads();
    if (!s_last) return;

    float* sacc = bins;
    for (int i = tid; i < 3 * 65 * NB; i += 1024)
        sacc[i] = atomicExch(&g_acc[i], 0.0f);
    __syncthreads();

    if (tid < NB) {
        float acc = 0.0f;
        for (int s = 1; s <= 64; s++) {
            float n  = sacc[0 * 520 + s * 8 + tid];
            float po = sacc[1 * 520 + s * 8 + tid];
            float pt = sacc[2 * 520 + s * 8 + tid];
            float f = n / sqrtf(po * pt + 1e-6f);
            acc += fminf(1.0f, fmaxf(-1.0f, f));
        }
        red[tid] = 1.0f - acc * (1.0f / 64.0f);
    }
    __syncthreads();
    if (tid == 0) {
        float m = 0.0f;
#pragma unroll
        for (int i = 0; i < NB; i++) m += red[i];
        out[0] = m * (1.0f / (float)NB);
        atomicExch(&g_done, 0u);
    }
}

// ---------------------------------------------------------------------------
extern "C" void kernel_launch(void* const* d_in, const int* in_sizes, int n_in,
                              void* d_out, int out_size) {
    const float* model_output = (const float*)d_in[0];
    const float* target       = (const float*)d_in[1];

    cudaFuncSetAttribute(k_fft_yz_reduce,
                         cudaFuncAttributeMaxDynamicSharedMemorySize, SMEM2);

    k_fft_x<<<8 * 128 * 2, 1024>>>(model_output, target);
    k_fft_yz_reduce<<<8 * 65, 1024, SMEM2>>>((float*)d_out);
}

// round 11
// speedup vs baseline: 1.9246x; 1.0389x over previous
#include <cuda_runtime.h>
#include <cuda_fp16.h>
#include <math.h>

#define VOL (128*128*128)          // 2^21
#define NB 8                        // batch*channels

// Packed spectra FFT(o + i*t): [vol][p][z][y] where plane p holds true kx=rev7(p)
__device__ __half2 g_ft[(size_t)NB * VOL];
// Accumulators: c3*520 + shell*8 + bc
__device__ float g_acc[3 * 65 * NB];
__device__ unsigned g_done;

__device__ __forceinline__ int rev5(int i) { return (int)(__brev((unsigned)i) >> 27); }
__device__ __forceinline__ int rev7(int i) { return (int)(__brev((unsigned)i) >> 25); }

// ===========================================================================
// fp16 twiddle tables. Twiddle stored as pair (wr,wr),(-wi,wi).
// The 1/sqrt(128) ortho scale is folded into the m=2 stage table (twS[3]).
struct __align__(8) h2pair { __half2 rr, ii; };
#define TABS_H (64 + 32 + 128)

__device__ __forceinline__ void init_tabs_h(h2pair* twA, h2pair* twB, h2pair* twS, int tid) {
    const float K = -0.04908738521234052f;   // -2*pi/128
    const float SC = 0.08838834764831845f;   // 1/sqrt(128)
    if (tid < 64) {
        float sv, cv; sincosf(K * (float)tid, &sv, &cv);
        twA[tid].rr = __floats2half2_rn(cv, cv);
        twA[tid].ii = __floats2half2_rn(-sv, sv);
    }
    if (tid < 32) {
        float sv, cv; sincosf(K * (float)(2 * tid), &sv, &cv);
        twB[tid].rr = __floats2half2_rn(cv, cv);
        twB[tid].ii = __floats2half2_rn(-sv, sv);
#pragma unroll
        for (int j = 0; j < 4; j++) {
            int m = 16 >> j;
            float c2 = 1.0f, s2 = 0.0f;
            if (tid & m) {
                int idx = (tid & (m - 1)) * (64 / m);
                sincosf(K * (float)idx, &s2, &c2);
            }
            float g = (j == 3) ? SC : 1.0f;    // fold ortho scale into m=2 stage
            twS[j * 32 + tid].rr = __floats2half2_rn(c2 * g, c2 * g);
            twS[j * 32 + tid].ii = __floats2half2_rn(-s2 * g, s2 * g);
        }
    }
}

__device__ __forceinline__ __half2 cmul_h(h2pair w, __half2 v) {
    return __hfma2(w.ii, __lowhigh2highlow(v), __hmul2(w.rr, v));
}
__device__ __forceinline__ __half2 shflx_h2(__half2 v, int m) {
    unsigned u = *reinterpret_cast<unsigned*>(&v);
    u = __shfl_xor_sync(0xffffffffu, u, m);
    return *reinterpret_cast<__half2*>(&u);
}
__device__ __forceinline__ __half2 sgn_h2(int hi) {
    unsigned u = hi ? 0xBC00BC00u : 0x3C003C00u;   // (-1,-1) : (1,1)
    return *reinterpret_cast<__half2*>(&u);
}
__device__ __forceinline__ __half2 conj_h2(__half2 v) {
    unsigned c = 0xBC003C00u;                      // (1, -1)
    return __hmul2(v, *reinterpret_cast<__half2*>(&c));
}

// TWO interleaved 128-pt DIF FFTs in fp16x2 (shared twiddles, 2x ILP).
// Slot (lane,r) holds x[lane+32r] in, sc*X[rev7(lane+32r)] out.
__device__ __forceinline__ void dif_fft128_h2(__half2 v[4], __half2 u[4], int lane,
        const h2pair* twA, const h2pair* twB, const h2pair* twS) {
    __half2 a, b;
    {
        h2pair w0 = twA[lane], w1 = twA[lane + 32];
        a = v[0]; b = v[2]; v[0] = __hadd2(a, b); v[2] = cmul_h(w0, __hsub2(a, b));
        a = u[0]; b = u[2]; u[0] = __hadd2(a, b); u[2] = cmul_h(w0, __hsub2(a, b));
        a = v[1]; b = v[3]; v[1] = __hadd2(a, b); v[3] = cmul_h(w1, __hsub2(a, b));
        a = u[1]; b = u[3]; u[1] = __hadd2(a, b); u[3] = cmul_h(w1, __hsub2(a, b));
    }
    {
        h2pair w0 = twB[lane];
        a = v[0]; b = v[1]; v[0] = __hadd2(a, b); v[1] = cmul_h(w0, __hsub2(a, b));
        a = v[2]; b = v[3]; v[2] = __hadd2(a, b); v[3] = cmul_h(w0, __hsub2(a, b));
        a = u[0]; b = u[1]; u[0] = __hadd2(a, b); u[1] = cmul_h(w0, __hsub2(a, b));
        a = u[2]; b = u[3]; u[2] = __hadd2(a, b); u[3] = cmul_h(w0, __hsub2(a, b));
    }
#pragma unroll
    for (int j = 0; j < 4; j++) {
        int m = 16 >> j;
        __half2 sg = sgn_h2(lane & m);
        h2pair wj = twS[j * 32 + lane];
#pragma unroll
        for (int r = 0; r < 4; r++) {
            __half2 o1 = shflx_h2(v[r], m);
            __half2 o2 = shflx_h2(u[r], m);
            v[r] = cmul_h(wj, __hfma2(sg, v[r], o1));
            u[r] = cmul_h(wj, __hfma2(sg, u[r], o2));
        }
    }
    {
        __half2 sg = sgn_h2(lane & 1);
#pragma unroll
        for (int r = 0; r < 4; r++) {
            __half2 o1 = shflx_h2(v[r], 1);
            __half2 o2 = shflx_h2(u[r], 1);
            v[r] = __hfma2(sg, v[r], o1);
            u[r] = __hfma2(sg, u[r], o2);
        }
    }
}

// ---------------------------------------------------------------------------
// Pass 1: pack P = o + i*t (fp16), x-FFT fp16 (2 rows per warp, interleaved),
// transposed to [vol][p][z][y].
__global__ void __launch_bounds__(1024) k_fft_x(const float* __restrict__ a_in,
                                                const float* __restrict__ b_in) {
    __shared__ h2pair tabs[TABS_H];
    __shared__ __half2 tile[64][129];
    h2pair* twA = tabs; h2pair* twB = tabs + 64; h2pair* twS = tabs + 96;
    int tid = threadIdx.x, lane = tid & 31, w = tid >> 5;
    init_tabs_h(twA, twB, twS, tid);

    unsigned b = blockIdx.x;              // 8 vols * 128 z * 2 ytiles = 2048
    unsigned ytile = b & 1u;
    unsigned z     = (b >> 1) & 127u;
    unsigned vol   = b >> 8;

    size_t off = (size_t)vol * VOL + (size_t)z * 16384 + (size_t)(ytile * 64 + w) * 128;
    const float* so = a_in + off;
    const float* st = b_in + off;
    __syncthreads();

    __half2 v[4], u[4];
#pragma unroll
    for (int r = 0; r < 4; r++) {
        v[r] = __floats2half2_rn(so[lane + 32 * r],        st[lane + 32 * r]);
        u[r] = __floats2half2_rn(so[lane + 32 * r + 4096], st[lane + 32 * r + 4096]);
    }
    dif_fft128_h2(v, u, lane, twA, twB, twS);

#pragma unroll
    for (int r = 0; r < 4; r++) {
        tile[w][lane + 32 * r]      = v[r];
        tile[w + 32][lane + 32 * r] = u[r];
    }
    __syncthreads();

    size_t base = (size_t)vol * VOL + (size_t)z * 128 + ytile * 64 + lane;
#pragma unroll
    for (int xi = 0; xi < 4; xi++) {
        int p = w * 4 + xi;               // bit-reversed kx label
        g_ft[base + (size_t)p * 16384]      = tile[lane][p];
        g_ft[base + (size_t)p * 16384 + 32] = tile[lane + 32][p];
    }
}

// ---------------------------------------------------------------------------
// Pass 2: per (bc, true-kx pair): y-FFT reads DIRECTLY from global (coalesced,
// L2-resident) into registers and writes results to smem; z-FFT in registers
// (column + conj-mirror column interleaved, same-lane Hermitian pairing);
// fp32 shell reduce. No staging round-trip.
#define SMEM2 (TABS_H * 8 + 2 * 128 * 129 * 4 + 32 * 196 * 4)

__global__ void __launch_bounds__(1024, 1) k_fft_yz_reduce(float* __restrict__ out) {
    extern __shared__ unsigned char smem_raw[];
    h2pair*  tabs = (h2pair*)smem_raw;
    h2pair*  twA = tabs; h2pair* twB = tabs + 64; h2pair* twS = tabs + 96;
    __half2* pA   = (__half2*)(tabs + TABS_H);            // [z][y] pitch 129
    __half2* pBs  = pA + 128 * 129;
    float*   bins = (float*)(pBs + 128 * 129);            // [warp][196]
    __shared__ bool s_last;
    __shared__ float red[NB];

    int tid = threadIdx.x, lane = tid & 31, w = tid >> 5;
    init_tabs_h(twA, twB, twS, tid);
    for (int i = tid; i < 32 * 196; i += 1024) bins[i] = 0.0f;

    unsigned bc  = blockIdx.x / 65;
    unsigned kx1 = blockIdx.x % 65;                       // true kx 0..64
    unsigned kx2 = (128u - kx1) & 127u;
    bool dual = (kx2 != kx1);
    int p1 = rev7((int)kx1), p2 = rev7((int)kx2);
    __half2* pB = dual ? pBs : pA;

    const __half2* gA = g_ft + ((size_t)bc * 128 + p1) * 16384;
    const __half2* gB = g_ft + ((size_t)bc * 128 + p2) * 16384;
    __syncthreads();                       // tables + bins ready

    // y-FFT: rows read straight from global, results to smem.
    if (dual) {
        // pair row z of plane A with row z of plane B (4 z's per warp)
#pragma unroll
        for (int i = 0; i < 4; i++) {
            int z = w + 32 * i;
            __half2 v[4], u[4];
#pragma unroll
            for (int r = 0; r < 4; r++) {
                v[r] = gA[z * 128 + lane + 32 * r];
                u[r] = gB[z * 128 + lane + 32 * r];
            }
            dif_fft128_h2(v, u, lane, twA, twB, twS);
#pragma unroll
            for (int r = 0; r < 4; r++) {
                pA [z * 129 + lane + 32 * r] = v[r];
                pBs[z * 129 + lane + 32 * r] = u[r];
            }
        }
    } else {
        // self-mirror plane: pair rows (w+64i, w+64i+32) within plane A
#pragma unroll
        for (int i = 0; i < 2; i++) {
            int z0 = w + 64 * i, z1 = z0 + 32;
            __half2 v[4], u[4];
#pragma unroll
            for (int r = 0; r < 4; r++) {
                v[r] = gA[z0 * 128 + lane + 32 * r];
                u[r] = gA[z1 * 128 + lane + 32 * r];
            }
            dif_fft128_h2(v, u, lane, twA, twB, twS);
#pragma unroll
            for (int r = 0; r < 4; r++) {
                pA[z0 * 129 + lane + 32 * r] = v[r];
                pA[z1 * 129 + lane + 32 * r] = u[r];
            }
        }
    }
    __syncthreads();

    // z-FFT (fp16, registers). Mirror value F(-k) via FFT of the CONJUGATED
    // mirror column (same slot as F(k)); conj folds into O/T sign flips.
    // slot (lane,r) holds kz = 4*rev5(lane) + {0,2,1,3}[r]
    int fx = (int)kx1; if (fx >= 64) fx -= 128;
    float cfac = dual ? 0.5f : 0.25f;     // z-norm inside the FFT scale
    float* mybins = bins + w * 196;

    int qz = rev5(lane);
    int kzv[4] = { 4 * qz, 4 * qz + 2, 4 * qz + 1, 4 * qz + 3 };
    int fzv[4];
#pragma unroll
    for (int r = 0; r < 4; r++) fzv[r] = (kzv[r] >= 64) ? kzv[r] - 128 : kzv[r];

#pragma unroll
    for (int i = 0; i < 4; i++) {
        int pyA = w + 32 * i;                 // column position (bit-reversed ky)
        int kyA = rev7(pyA);
        int fy = (kyA >= 64) ? kyA - 128 : kyA;
        int fxy2 = fx * fx + fy * fy;
        if (fxy2 > 4224) continue;            // no shell <= 64 possible (warp-uniform)
        int pyB = rev7((128 - kyA) & 127);

        __half2 va[4], vh[4];
#pragma unroll
        for (int r = 0; r < 4; r++) {
            va[r] = pA[(lane + 32 * r) * 129 + pyA];
            vh[r] = conj_h2(pB[(lane + 32 * r) * 129 + pyB]);
        }
        dif_fft128_h2(va, vh, lane, twA, twB, twS);

#pragma unroll
        for (int r = 0; r < 4; r++) {
            int r2 = fzv[r] * fzv[r] + fxy2;
            int sh = (int)sqrtf((float)r2);    // exact truncation
            if (sh <= 64) {
                float2 F = __half22float2(va[r]);
                float2 H = __half22float2(vh[r]);   // H = conj(F(-k))
                float Ox = F.x + H.x, Oy = F.y + H.y;   // 2*O
                float Tx = F.y - H.y, Ty = H.x - F.x;   // 2*T
                atomicAdd(&mybins[sh * 3 + 0], Ox * Tx + Oy * Ty);
                atomicAdd(&mybins[sh * 3 + 1], Ox * Ox + Oy * Oy);
                atomicAdd(&mybins[sh * 3 + 2], Tx * Tx + Ty * Ty);
            }
        }
    }
    __syncthreads();

    // fold per-warp bins -> global accumulators (cfac applied once here)
    if (tid < 195) {
        float s = 0.0f;
#pragma unroll
        for (int ww = 0; ww < 32; ww++) s += bins[ww * 196 + tid];
        int sh = tid / 3, c3 = tid % 3;
        atomicAdd(&g_acc[c3 * 520 + sh * 8 + bc], s * cfac);
    }
    __syncthreads();

    // last block computes loss and resets state (graph-replay safe)
    if (tid == 0) {
        __threadfence();
        unsigned old = atomicAdd(&g_done, 1u);
        s_last = (old == gridDim.x - 1);
    }
    __syncthreads();
    if (!s_last) return;

    float* sacc = bins;
    for (int i = tid; i < 3 * 65 * NB; i += 1024)
        sacc[i] = atomicExch(&g_acc[i], 0.0f);
    __syncthreads();

    if (tid < NB) {
        float acc = 0.0f;
        for (int s = 1; s <= 64; s++) {
            float n  = sacc[0 * 520 + s * 8 + tid];
            float po = sacc[1 * 520 + s * 8 + tid];
            float pt = sacc[2 * 520 + s * 8 + tid];
            float f = n / sqrtf(po * pt + 1e-6f);
            acc += fminf(1.0f, fmaxf(-1.0f, f));
        }
        red[tid] = 1.0f - acc * (1.0f / 64.0f);
    }
    __syncthreads();
    if (tid == 0) {
        float m = 0.0f;
#pragma unroll
        for (int i = 0; i < NB; i++) m += red[i];
        out[0] = m * (1.0f / (float)NB);
        atomicExch(&g_done, 0u);
    }
}

// ---------------------------------------------------------------------------
extern "C" void kernel_launch(void* const* d_in, const int* in_sizes, int n_in,
                              void* d_out, int out_size) {
    const float* model_output = (const float*)d_in[0];
    const float* target       = (const float*)d_in[1];

    cudaFuncSetAttribute(k_fft_yz_reduce,
                         cudaFuncAttributeMaxDynamicSharedMemorySize, SMEM2);

    k_fft_x<<<8 * 128 * 2, 1024>>>(model_output, target);
    k_fft_yz_reduce<<<8 * 65, 1024, SMEM2>>>((float*)d_out);
}